// round 10
// baseline (speedup 1.0000x reference)
#include <cuda_runtime.h>

#define N_NODES 50000
#define N_EDGES 200000
#define IN_C    32
#define HID     32
#define OUT_C   16
#define EDGE_DIM 8
#define LN_EPS  1e-5f

typedef unsigned long long u64;

// scatter accumulator; zero-initialized at module load; node_kernel re-zeroes
// it after consuming, so the invariant holds across graph replays.
__device__ float g_agg[N_NODES * HID];

__device__ __forceinline__ u64 ffma2(u64 a, u64 b, u64 c) {
    u64 d;
    asm("fma.rn.f32x2 %0, %1, %2, %3;" : "=l"(d) : "l"(a), "l"(b), "l"(c));
    return d;
}
__device__ __forceinline__ u64 add2(u64 a, u64 b) {
    u64 d;
    asm("add.rn.f32x2 %0, %1, %2;" : "=l"(d) : "l"(a), "l"(b));
    return d;
}
__device__ __forceinline__ u64 dup2(float s) {
    unsigned u = __float_as_uint(s);
    return ((u64)u << 32) | (u64)u;
}
__device__ __forceinline__ u64 pack2(float lo, float hi) {
    return ((u64)__float_as_uint(hi) << 32) | (u64)__float_as_uint(lo);
}
__device__ __forceinline__ float lo2(u64 v) { return __uint_as_float((unsigned)v); }
__device__ __forceinline__ float hi2(u64 v) { return __uint_as_float((unsigned)(v >> 32)); }
// packed relu via FMNMX on the two halves (register pair aliasing: pack free)
__device__ __forceinline__ u64 relu2(u64 v) {
    return pack2(fmaxf(lo2(v), 0.f), fmaxf(hi2(v), 0.f));
}

// ---------------------------------------------------------------------------
// Edge kernel (best measured configuration — UNCHANGED from R9).
// ---------------------------------------------------------------------------
__global__ __launch_bounds__(256) void edge_kernel(
    const float* __restrict__ x,
    const int*   __restrict__ edge_index,
    const float* __restrict__ edge_attr,
    const float* __restrict__ nn_w,
    const float* __restrict__ nn_b)
{
    __shared__ u64   sw2[IN_C * EDGE_DIM * 16];  // 4096 u64 = 32 KB
    __shared__ u64   sb2[IN_C * 16];             //  512 u64 =  4 KB
    __shared__ float xs_s[8][8][IN_C];           // warp x edge x feat = 8 KB

    const int tid = threadIdx.x;

    for (int idx = tid; idx < EDGE_DIM * 512; idx += 256) {
        const int d = idx >> 9;
        const int j = idx & 511;
        const int i = j >> 4;
        const int p = j & 15;
        const float2 v = *(const float2*)(nn_w + d * (IN_C * HID) + i * HID + 2 * p);
        sw2[(i * EDGE_DIM + d) * 16 + p] = pack2(v.x, v.y);
    }
    for (int idx = tid; idx < 512; idx += 256) {
        const int i = idx >> 4;
        const int p = idx & 15;
        const float2 v = *(const float2*)(nn_b + i * HID + 2 * p);
        sb2[i * 16 + p] = pack2(v.x, v.y);
    }
    __syncthreads();

    const int lane = tid & 31;
    const int p    = lane & 15;
    const int eh   = lane >> 4;
    const int warp = tid >> 5;
    const int gwarp = blockIdx.x * 8 + warp;
    const int warpsTotal = gridDim.x * 8;
    const int nGroups = N_EDGES / 8;  // 25000, exact

    for (int g = gwarp; g < nGroups; g += warpsTotal) {
        const int e0 = g * 8;

        #pragma unroll
        for (int e = 0; e < 8; ++e) {
            const int s = edge_index[e0 + e];
            xs_s[warp][e][lane] = x[(size_t)s * IN_C + lane];
        }

        const int eb = e0 + eh * 4;
        int dst[4];
        u64 ea2[4][8];
        #pragma unroll
        for (int e = 0; e < 4; ++e) {
            dst[e] = edge_index[N_EDGES + eb + e];
            const float4 lo = *(const float4*)(edge_attr + (size_t)(eb + e) * EDGE_DIM);
            const float4 hi = *(const float4*)(edge_attr + (size_t)(eb + e) * EDGE_DIM + 4);
            ea2[e][0] = dup2(lo.x); ea2[e][1] = dup2(lo.y);
            ea2[e][2] = dup2(lo.z); ea2[e][3] = dup2(lo.w);
            ea2[e][4] = dup2(hi.x); ea2[e][5] = dup2(hi.y);
            ea2[e][6] = dup2(hi.z); ea2[e][7] = dup2(hi.w);
        }
        __syncwarp();

        u64 msg2[4] = {0ull, 0ull, 0ull, 0ull};

        #pragma unroll 8
        for (int i = 0; i < IN_C; ++i) {
            u64 w[8];
            #pragma unroll
            for (int d = 0; d < 8; ++d) w[d] = sw2[(i * 8 + d) * 16 + p];
            const u64 b = sb2[i * 16 + p];
            #pragma unroll
            for (int e = 0; e < 4; ++e) {
                const u64 xv = dup2(xs_s[warp][eh * 4 + e][i]);  // smem bcast
                u64 a = b;
                #pragma unroll
                for (int d = 0; d < 8; ++d) a = ffma2(ea2[e][d], w[d], a);
                a = relu2(a);
                msg2[e] = ffma2(xv, a, msg2[e]);
            }
        }

        #pragma unroll
        for (int e = 0; e < 4; ++e) {
            float* base = &g_agg[(size_t)dst[e] * HID + 2 * p];
            atomicAdd(base,     lo2(msg2[e]));
            atomicAdd(base + 1, hi2(msg2[e]));
        }
        __syncwarp();
    }
}

// ---------------------------------------------------------------------------
// Node kernel, 4 lanes per node, MIO-diet version:
//  - full x row loaded per lane (L1 quad-broadcast) -> no x-broadcast SHFLs
//  - root/lin_w smem reads widened to LDS.128
//  - LN + final-linear reductions remain quad shfl.xor (36 SHFLs total)
// Resets g_agg after consuming (replaces zero kernel).
// ---------------------------------------------------------------------------
__global__ __launch_bounds__(256) void node_kernel(
    const float* __restrict__ x,
    const float* __restrict__ root,
    const float* __restrict__ bias,
    const float* __restrict__ norm_w,
    const float* __restrict__ norm_b,
    const float* __restrict__ lin_w,
    const float* __restrict__ lin_b,
    float* __restrict__ out)
{
    __shared__ u64 root2[IN_C * 16];   // root packed: [i][pair]; 16B-aligned rows
    __shared__ u64 lw2[HID * 8];       // lin_w packed: [k][opair]
    __shared__ u64 bias2[16], nw2[16], nb2[16];
    __shared__ float lb_s[OUT_C];

    const int tid = threadIdx.x;
    for (int idx = tid; idx < IN_C * 16; idx += 256) {
        const int i = idx >> 4, pr = idx & 15;
        const float2 v = *(const float2*)(root + i * HID + 2 * pr);
        root2[idx] = pack2(v.x, v.y);
    }
    for (int idx = tid; idx < HID * 8; idx += 256) {
        const int k = idx >> 3, op = idx & 7;
        const float2 v = *(const float2*)(lin_w + k * OUT_C + 2 * op);
        lw2[idx] = pack2(v.x, v.y);
    }
    if (tid < 16) {
        const float2 b = *(const float2*)(bias + 2 * tid);
        const float2 w = *(const float2*)(norm_w + 2 * tid);
        const float2 nb = *(const float2*)(norm_b + 2 * tid);
        bias2[tid] = pack2(b.x, b.y);
        nw2[tid]   = pack2(w.x, w.y);
        nb2[tid]   = pack2(nb.x, nb.y);
    }
    if (tid < OUT_C) lb_s[tid] = lin_b[tid];
    __syncthreads();

    const int t = blockIdx.x * 256 + tid;
    const int rawNode = t >> 2;
    const bool valid = rawNode < N_NODES;
    const int node = valid ? rawNode : (N_NODES - 1);
    const int sub  = t & 3;
    const int fb   = sub * 8;            // feature base
    const int pb   = sub * 4;            // pair base

    // full x row for this node (quad lanes share L1 lines)
    const float4* xp = (const float4*)(x + (size_t)node * IN_C);
    float xf[IN_C];
    #pragma unroll
    for (int q = 0; q < 8; ++q) {
        const float4 v = xp[q];
        xf[q * 4 + 0] = v.x; xf[q * 4 + 1] = v.y;
        xf[q * 4 + 2] = v.z; xf[q * 4 + 3] = v.w;
    }

    const float4* aggp = (const float4*)(g_agg + (size_t)node * HID + fb);
    const float4  a0 = aggp[0], a1 = aggp[1];

    u64 h2[4];
    h2[0] = add2(pack2(a0.x, a0.y), bias2[pb + 0]);
    h2[1] = add2(pack2(a0.z, a0.w), bias2[pb + 1]);
    h2[2] = add2(pack2(a1.x, a1.y), bias2[pb + 2]);
    h2[3] = add2(pack2(a1.z, a1.w), bias2[pb + 3]);

    // h += x @ root  (LDS.128 pairs; dup2 on ALU pipe, no SHFL)
    const ulonglong2* r2 = (const ulonglong2*)root2;
    #pragma unroll
    for (int i = 0; i < IN_C; ++i) {
        const u64 xi2 = dup2(xf[i]);
        const ulonglong2 ra = r2[i * 8 + 2 * sub + 0];   // pairs pb+0, pb+1
        const ulonglong2 rb = r2[i * 8 + 2 * sub + 1];   // pairs pb+2, pb+3
        h2[0] = ffma2(xi2, ra.x, h2[0]);
        h2[1] = ffma2(xi2, ra.y, h2[1]);
        h2[2] = ffma2(xi2, rb.x, h2[2]);
        h2[3] = ffma2(xi2, rb.y, h2[3]);
    }

    // LayerNorm across the quad
    float s = 0.f;
    #pragma unroll
    for (int j = 0; j < 4; ++j) s += lo2(h2[j]) + hi2(h2[j]);
    s += __shfl_xor_sync(0xffffffffu, s, 1);
    s += __shfl_xor_sync(0xffffffffu, s, 2);
    const float mu = s * (1.0f / HID);
    const u64 negmu2 = dup2(-mu);

    u64 vacc = 0ull;
    u64 d2[4];
    #pragma unroll
    for (int j = 0; j < 4; ++j) {
        d2[j] = add2(h2[j], negmu2);
        vacc = ffma2(d2[j], d2[j], vacc);
    }
    float v = lo2(vacc) + hi2(vacc);
    v += __shfl_xor_sync(0xffffffffu, v, 1);
    v += __shfl_xor_sync(0xffffffffu, v, 2);
    const float inv = rsqrtf(v * (1.0f / HID) + LN_EPS);
    const u64 inv2 = dup2(inv);

    float h[8];
    #pragma unroll
    for (int j = 0; j < 4; ++j) {
        u64 t2 = ffma2(d2[j], inv2, 0ull);              // d * inv
        t2 = ffma2(t2, nw2[pb + j], nb2[pb + j]);
        h[2 * j + 0] = fmaxf(lo2(t2), 0.f);
        h[2 * j + 1] = fmaxf(hi2(t2), 0.f);
    }

    // partial final linear (LDS.128 weight pairs)
    u64 res2[8];
    #pragma unroll
    for (int op = 0; op < 8; ++op) res2[op] = 0ull;
    const ulonglong2* l2 = (const ulonglong2*)lw2;
    #pragma unroll
    for (int k = 0; k < 8; ++k) {
        const u64 hv2 = dup2(h[k]);
        #pragma unroll
        for (int q = 0; q < 4; ++q) {
            const ulonglong2 w = l2[(fb + k) * 4 + q];
            res2[2 * q + 0] = ffma2(hv2, w.x, res2[2 * q + 0]);
            res2[2 * q + 1] = ffma2(hv2, w.y, res2[2 * q + 1]);
        }
    }
    // reduce across quad
    float res[OUT_C];
    #pragma unroll
    for (int op = 0; op < 8; ++op) {
        float rl = lo2(res2[op]), rh = hi2(res2[op]);
        rl += __shfl_xor_sync(0xffffffffu, rl, 1);
        rl += __shfl_xor_sync(0xffffffffu, rl, 2);
        rh += __shfl_xor_sync(0xffffffffu, rh, 1);
        rh += __shfl_xor_sync(0xffffffffu, rh, 2);
        res[2 * op + 0] = rl;
        res[2 * op + 1] = rh;
    }

    // reset accumulator for the next replay (after consumption)
    if (valid) {
        float4* ragg = (float4*)(g_agg + (size_t)node * HID + fb);
        const float4 z4 = make_float4(0.f, 0.f, 0.f, 0.f);
        ragg[0] = z4; ragg[1] = z4;
        // lane sub writes outputs [4*sub, 4*sub+4)
        float* op = out + (size_t)node * OUT_C;
        #pragma unroll
        for (int oo = 0; oo < OUT_C; ++oo)
            if ((oo >> 2) == sub) op[oo] = res[oo] + lb_s[oo];
    }
}

extern "C" void kernel_launch(void* const* d_in, const int* in_sizes, int n_in,
                              void* d_out, int out_size) {
    const float* x          = (const float*)d_in[0];
    const int*   edge_index = (const int*)  d_in[1];
    const float* edge_attr  = (const float*)d_in[2];
    const float* nn_w       = (const float*)d_in[3];
    const float* nn_b       = (const float*)d_in[4];
    const float* root       = (const float*)d_in[5];
    const float* bias       = (const float*)d_in[6];
    const float* norm_w     = (const float*)d_in[7];
    const float* norm_b     = (const float*)d_in[8];
    const float* lin_w      = (const float*)d_in[9];
    const float* lin_b      = (const float*)d_in[10];
    float* out = (float*)d_out;

    edge_kernel<<<592, 256>>>(x, edge_index, edge_attr, nn_w, nn_b);
    node_kernel<<<(N_NODES * 4 + 255) / 256, 256>>>(x, root, bias, norm_w, norm_b,
                                                    lin_w, lin_b, out);
}

// round 11
// speedup vs baseline: 1.4661x; 1.4661x over previous
#include <cuda_runtime.h>

#define N_NODES 50000
#define N_EDGES 200000
#define IN_C    32
#define HID     32
#define OUT_C   16
#define EDGE_DIM 8
#define LN_EPS  1e-5f

typedef unsigned long long u64;

// scatter accumulator; zero-initialized at module load; node_kernel re-zeroes
// it after consuming, so the invariant holds across graph replays.
__device__ float g_agg[N_NODES * HID];

__device__ __forceinline__ u64 ffma2(u64 a, u64 b, u64 c) {
    u64 d;
    asm("fma.rn.f32x2 %0, %1, %2, %3;" : "=l"(d) : "l"(a), "l"(b), "l"(c));
    return d;
}
__device__ __forceinline__ u64 add2(u64 a, u64 b) {
    u64 d;
    asm("add.rn.f32x2 %0, %1, %2;" : "=l"(d) : "l"(a), "l"(b));
    return d;
}
__device__ __forceinline__ u64 dup2(float s) {
    unsigned u = __float_as_uint(s);
    return ((u64)u << 32) | (u64)u;
}
__device__ __forceinline__ u64 pack2(float lo, float hi) {
    return ((u64)__float_as_uint(hi) << 32) | (u64)__float_as_uint(lo);
}
__device__ __forceinline__ float lo2(u64 v) { return __uint_as_float((unsigned)v); }
__device__ __forceinline__ float hi2(u64 v) { return __uint_as_float((unsigned)(v >> 32)); }

__device__ __forceinline__ unsigned tf32_of(float f) {
    unsigned r;
    asm("cvt.rna.tf32.f32 %0, %1;" : "=r"(r) : "f"(f));
    return r;
}

// ---------------------------------------------------------------------------
// Edge kernel: tf32 mma.sync MLP + scalar contraction + atomic scatter.
// Warp handles 16 edges/group. For tile t (cols 8t..8t+7 of the 1024-wide
// MLP output, i = t>>2, o = 8*(t&3)+2*t4+j):
//   D[16x8] = relu( A[16x8](ea, tf32) x B[8x8](nn_w, tf32) + bias )
//   msg[e,o] += x[src[e]][i] * D
// Fragment mapping (m16n8k8.row.col): lane g4=lane>>2, t4=lane&3;
//   a0:(g4,t4) a1:(g4+8,t4) a2:(g4,t4+4) a3:(g4+8,t4+4)
//   b0:(k=t4,n=g4) b1:(k=t4+4,n=g4)   c/d: (g4,2t4),(g4,2t4+1),(+8 rows)
// ---------------------------------------------------------------------------
__global__ __launch_bounds__(128) void edge_kernel(
    const float* __restrict__ x,
    const int*   __restrict__ edge_index,
    const float* __restrict__ edge_attr,
    const float* __restrict__ nn_w,
    const float* __restrict__ nn_b)
{
    __shared__ unsigned sb0[1024 * 4];       // b0: tf32(nn_w[k][col]), idx=col*4+k      16 KB
    __shared__ unsigned sb1[1024 * 4];       // b1: tf32(nn_w[k+4][col])                 16 KB
    __shared__ u64      sbias[512];          // (bias[2p], bias[2p+1]) fp32 pairs         4 KB
    __shared__ float    xs[4][16][33];       // [warp][edge][feat], padded stride       8.25 KB
    __shared__ int      ssrc[4][16], sdst[4][16];

    const int tid = threadIdx.x;

    for (int idx = tid; idx < 4096; idx += 128) {
        const int col = idx >> 2, k = idx & 3;
        sb0[idx] = tf32_of(nn_w[k * 1024 + col]);
        sb1[idx] = tf32_of(nn_w[(k + 4) * 1024 + col]);
    }
    for (int idx = tid; idx < 512; idx += 128) {
        const float2 v = *(const float2*)(nn_b + 2 * idx);
        sbias[idx] = pack2(v.x, v.y);
    }
    __syncthreads();

    const int lane = tid & 31;
    const int warp = tid >> 5;
    const int g4 = lane >> 2;
    const int t4 = lane & 3;
    const int nGroups = N_EDGES / 16;   // 12500, exact

    for (int g = blockIdx.x * 4 + warp; g < nGroups; g += gridDim.x * 4) {
        const int e0 = g * 16;

        if (lane < 16) {
            ssrc[warp][lane] = edge_index[e0 + lane];
            sdst[warp][lane] = edge_index[N_EDGES + e0 + lane];
        }
        __syncwarp();

        // stage x rows: lane -> edge lane>>1, half lane&1 (16 feats)
        {
            const int e = lane >> 1, hf = lane & 1;
            const float4* xr = (const float4*)(x + (size_t)ssrc[warp][e] * IN_C + hf * 16);
            float* dx = &xs[warp][e][hf * 16];
            #pragma unroll
            for (int q = 0; q < 4; ++q) {
                const float4 v = xr[q];
                dx[q * 4 + 0] = v.x; dx[q * 4 + 1] = v.y;
                dx[q * 4 + 2] = v.z; dx[q * 4 + 3] = v.w;
            }
        }

        // A fragments from gmem (small, L1-hot)
        const float* eaP = edge_attr + (size_t)e0 * EDGE_DIM;
        const unsigned a0 = tf32_of(eaP[g4 * 8 + t4]);
        const unsigned a1 = tf32_of(eaP[(g4 + 8) * 8 + t4]);
        const unsigned a2 = tf32_of(eaP[g4 * 8 + t4 + 4]);
        const unsigned a3 = tf32_of(eaP[(g4 + 8) * 8 + t4 + 4]);
        __syncwarp();

        const int dstA = sdst[warp][g4] * HID;
        const int dstB = sdst[warp][g4 + 8] * HID;

        float msgA[8], msgB[8];
        #pragma unroll
        for (int m = 0; m < 8; ++m) { msgA[m] = 0.f; msgB[m] = 0.f; }

        #pragma unroll 4
        for (int i = 0; i < IN_C; ++i) {
            const float xv0 = xs[warp][g4][i];
            const float xv1 = xs[warp][g4 + 8][i];
            #pragma unroll
            for (int c = 0; c < 4; ++c) {
                const int t = i * 4 + c;
                const int colb = (8 * t + g4) * 4 + t4;
                const unsigned b0 = sb0[colb];
                const unsigned b1 = sb1[colb];
                const u64 cb = sbias[4 * t + t4];
                float d0 = lo2(cb), d1 = hi2(cb), d2 = d0, d3 = d1;
                asm("mma.sync.aligned.m16n8k8.row.col.f32.tf32.tf32.f32 "
                    "{%0,%1,%2,%3}, {%4,%5,%6,%7}, {%8,%9}, {%0,%1,%2,%3};"
                    : "+f"(d0), "+f"(d1), "+f"(d2), "+f"(d3)
                    : "r"(a0), "r"(a1), "r"(a2), "r"(a3), "r"(b0), "r"(b1));
                d0 = fmaxf(d0, 0.f); d1 = fmaxf(d1, 0.f);
                d2 = fmaxf(d2, 0.f); d3 = fmaxf(d3, 0.f);
                msgA[2 * c + 0] = fmaf(xv0, d0, msgA[2 * c + 0]);
                msgA[2 * c + 1] = fmaf(xv0, d1, msgA[2 * c + 1]);
                msgB[2 * c + 0] = fmaf(xv1, d2, msgB[2 * c + 0]);
                msgB[2 * c + 1] = fmaf(xv1, d3, msgB[2 * c + 1]);
            }
        }

        #pragma unroll
        for (int c = 0; c < 4; ++c) {
            #pragma unroll
            for (int j = 0; j < 2; ++j) {
                const int o = 8 * c + 2 * t4 + j;
                atomicAdd(&g_agg[dstA + o], msgA[2 * c + j]);
                atomicAdd(&g_agg[dstB + o], msgB[2 * c + j]);
            }
        }
        __syncwarp();   // protect ssrc/xs before next iteration's overwrite
    }
}

// ---------------------------------------------------------------------------
// Node kernel (unchanged from R10 measured config).
// ---------------------------------------------------------------------------
__global__ __launch_bounds__(256) void node_kernel(
    const float* __restrict__ x,
    const float* __restrict__ root,
    const float* __restrict__ bias,
    const float* __restrict__ norm_w,
    const float* __restrict__ norm_b,
    const float* __restrict__ lin_w,
    const float* __restrict__ lin_b,
    float* __restrict__ out)
{
    __shared__ u64 root2[IN_C * 16];
    __shared__ u64 lw2[HID * 8];
    __shared__ u64 bias2[16], nw2[16], nb2[16];
    __shared__ float lb_s[OUT_C];

    const int tid = threadIdx.x;
    for (int idx = tid; idx < IN_C * 16; idx += 256) {
        const int i = idx >> 4, pr = idx & 15;
        const float2 v = *(const float2*)(root + i * HID + 2 * pr);
        root2[idx] = pack2(v.x, v.y);
    }
    for (int idx = tid; idx < HID * 8; idx += 256) {
        const int k = idx >> 3, op = idx & 7;
        const float2 v = *(const float2*)(lin_w + k * OUT_C + 2 * op);
        lw2[idx] = pack2(v.x, v.y);
    }
    if (tid < 16) {
        const float2 b = *(const float2*)(bias + 2 * tid);
        const float2 w = *(const float2*)(norm_w + 2 * tid);
        const float2 nb = *(const float2*)(norm_b + 2 * tid);
        bias2[tid] = pack2(b.x, b.y);
        nw2[tid]   = pack2(w.x, w.y);
        nb2[tid]   = pack2(nb.x, nb.y);
    }
    if (tid < OUT_C) lb_s[tid] = lin_b[tid];
    __syncthreads();

    const int t = blockIdx.x * 256 + tid;
    const int rawNode = t >> 2;
    const bool valid = rawNode < N_NODES;
    const int node = valid ? rawNode : (N_NODES - 1);
    const int sub  = t & 3;
    const int fb   = sub * 8;
    const int pb   = sub * 4;

    const float4* xp = (const float4*)(x + (size_t)node * IN_C);
    float xf[IN_C];
    #pragma unroll
    for (int q = 0; q < 8; ++q) {
        const float4 v = xp[q];
        xf[q * 4 + 0] = v.x; xf[q * 4 + 1] = v.y;
        xf[q * 4 + 2] = v.z; xf[q * 4 + 3] = v.w;
    }

    const float4* aggp = (const float4*)(g_agg + (size_t)node * HID + fb);
    const float4  a0 = aggp[0], a1 = aggp[1];

    u64 h2[4];
    h2[0] = add2(pack2(a0.x, a0.y), bias2[pb + 0]);
    h2[1] = add2(pack2(a0.z, a0.w), bias2[pb + 1]);
    h2[2] = add2(pack2(a1.x, a1.y), bias2[pb + 2]);
    h2[3] = add2(pack2(a1.z, a1.w), bias2[pb + 3]);

    const ulonglong2* r2 = (const ulonglong2*)root2;
    #pragma unroll
    for (int i = 0; i < IN_C; ++i) {
        const u64 xi2 = dup2(xf[i]);
        const ulonglong2 ra = r2[i * 8 + 2 * sub + 0];
        const ulonglong2 rb = r2[i * 8 + 2 * sub + 1];
        h2[0] = ffma2(xi2, ra.x, h2[0]);
        h2[1] = ffma2(xi2, ra.y, h2[1]);
        h2[2] = ffma2(xi2, rb.x, h2[2]);
        h2[3] = ffma2(xi2, rb.y, h2[3]);
    }

    float s = 0.f;
    #pragma unroll
    for (int j = 0; j < 4; ++j) s += lo2(h2[j]) + hi2(h2[j]);
    s += __shfl_xor_sync(0xffffffffu, s, 1);
    s += __shfl_xor_sync(0xffffffffu, s, 2);
    const float mu = s * (1.0f / HID);
    const u64 negmu2 = dup2(-mu);

    u64 vacc = 0ull;
    u64 d2[4];
    #pragma unroll
    for (int j = 0; j < 4; ++j) {
        d2[j] = add2(h2[j], negmu2);
        vacc = ffma2(d2[j], d2[j], vacc);
    }
    float v = lo2(vacc) + hi2(vacc);
    v += __shfl_xor_sync(0xffffffffu, v, 1);
    v += __shfl_xor_sync(0xffffffffu, v, 2);
    const float inv = rsqrtf(v * (1.0f / HID) + LN_EPS);
    const u64 inv2 = dup2(inv);

    float h[8];
    #pragma unroll
    for (int j = 0; j < 4; ++j) {
        u64 t2 = ffma2(d2[j], inv2, 0ull);
        t2 = ffma2(t2, nw2[pb + j], nb2[pb + j]);
        h[2 * j + 0] = fmaxf(lo2(t2), 0.f);
        h[2 * j + 1] = fmaxf(hi2(t2), 0.f);
    }

    u64 res2[8];
    #pragma unroll
    for (int op = 0; op < 8; ++op) res2[op] = 0ull;
    const ulonglong2* l2 = (const ulonglong2*)lw2;
    #pragma unroll
    for (int k = 0; k < 8; ++k) {
        const u64 hv2 = dup2(h[k]);
        #pragma unroll
        for (int q = 0; q < 4; ++q) {
            const ulonglong2 w = l2[(fb + k) * 4 + q];
            res2[2 * q + 0] = ffma2(hv2, w.x, res2[2 * q + 0]);
            res2[2 * q + 1] = ffma2(hv2, w.y, res2[2 * q + 1]);
        }
    }
    float res[OUT_C];
    #pragma unroll
    for (int op = 0; op < 8; ++op) {
        float rl = lo2(res2[op]), rh = hi2(res2[op]);
        rl += __shfl_xor_sync(0xffffffffu, rl, 1);
        rl += __shfl_xor_sync(0xffffffffu, rl, 2);
        rh += __shfl_xor_sync(0xffffffffu, rh, 1);
        rh += __shfl_xor_sync(0xffffffffu, rh, 2);
        res[2 * op + 0] = rl;
        res[2 * op + 1] = rh;
    }

    if (valid) {
        float4* ragg = (float4*)(g_agg + (size_t)node * HID + fb);
        const float4 z4 = make_float4(0.f, 0.f, 0.f, 0.f);
        ragg[0] = z4; ragg[1] = z4;
        float* op = out + (size_t)node * OUT_C;
        #pragma unroll
        for (int oo = 0; oo < OUT_C; ++oo)
            if ((oo >> 2) == sub) op[oo] = res[oo] + lb_s[oo];
    }
}

extern "C" void kernel_launch(void* const* d_in, const int* in_sizes, int n_in,
                              void* d_out, int out_size) {
    const float* x          = (const float*)d_in[0];
    const int*   edge_index = (const int*)  d_in[1];
    const float* edge_attr  = (const float*)d_in[2];
    const float* nn_w       = (const float*)d_in[3];
    const float* nn_b       = (const float*)d_in[4];
    const float* root       = (const float*)d_in[5];
    const float* bias       = (const float*)d_in[6];
    const float* norm_w     = (const float*)d_in[7];
    const float* norm_b     = (const float*)d_in[8];
    const float* lin_w      = (const float*)d_in[9];
    const float* lin_b      = (const float*)d_in[10];
    float* out = (float*)d_out;

    edge_kernel<<<592, 128>>>(x, edge_index, edge_attr, nn_w, nn_b);
    node_kernel<<<(N_NODES * 4 + 255) / 256, 256>>>(x, root, bias, norm_w, norm_b,
                                                    lin_w, lin_b, out);
}

// round 12
// speedup vs baseline: 1.8099x; 1.2346x over previous
#include <cuda_runtime.h>

#define N_NODES 50000
#define N_EDGES 200000
#define IN_C    32
#define HID     32
#define OUT_C   16
#define EDGE_DIM 8
#define LN_EPS  1e-5f

typedef unsigned long long u64;

// scatter accumulator; zero-initialized at module load; node_kernel re-zeroes
// it after consuming, so the invariant holds across graph replays.
__device__ float g_agg[N_NODES * HID];

__device__ __forceinline__ u64 ffma2(u64 a, u64 b, u64 c) {
    u64 d;
    asm("fma.rn.f32x2 %0, %1, %2, %3;" : "=l"(d) : "l"(a), "l"(b), "l"(c));
    return d;
}
__device__ __forceinline__ u64 add2(u64 a, u64 b) {
    u64 d;
    asm("add.rn.f32x2 %0, %1, %2;" : "=l"(d) : "l"(a), "l"(b));
    return d;
}
__device__ __forceinline__ u64 dup2(float s) {
    unsigned u = __float_as_uint(s);
    return ((u64)u << 32) | (u64)u;
}
__device__ __forceinline__ u64 pack2(float lo, float hi) {
    return ((u64)__float_as_uint(hi) << 32) | (u64)__float_as_uint(lo);
}
__device__ __forceinline__ float lo2(u64 v) { return __uint_as_float((unsigned)v); }
__device__ __forceinline__ float hi2(u64 v) { return __uint_as_float((unsigned)(v >> 32)); }

__device__ __forceinline__ unsigned tf32_of(float f) {
    unsigned r;
    asm("cvt.rna.tf32.f32 %0, %1;" : "=r"(r) : "f"(f));
    return r;
}
// paired no-return reduction (8B-aligned)
__device__ __forceinline__ void red2(float* p, float a, float b) {
    asm volatile("red.global.add.v2.f32 [%0], {%1, %2};"
        :: "l"(p), "f"(a), "f"(b) : "memory");
}

// ---------------------------------------------------------------------------
// Edge kernel: tf32 mma.sync MLP + scalar contraction + v2 reduction scatter.
// (R11 structure; only the scatter changed: 16 scalar atomics -> 8 red.v2)
// ---------------------------------------------------------------------------
__global__ __launch_bounds__(128) void edge_kernel(
    const float* __restrict__ x,
    const int*   __restrict__ edge_index,
    const float* __restrict__ edge_attr,
    const float* __restrict__ nn_w,
    const float* __restrict__ nn_b)
{
    __shared__ unsigned sb0[1024 * 4];       // b0: tf32(nn_w[k][col]), idx=col*4+k
    __shared__ unsigned sb1[1024 * 4];       // b1: tf32(nn_w[k+4][col])
    __shared__ u64      sbias[512];          // (bias[2p], bias[2p+1]) fp32 pairs
    __shared__ float    xs[4][16][33];       // [warp][edge][feat], padded stride
    __shared__ int      ssrc[4][16], sdst[4][16];

    const int tid = threadIdx.x;

    for (int idx = tid; idx < 4096; idx += 128) {
        const int col = idx >> 2, k = idx & 3;
        sb0[idx] = tf32_of(nn_w[k * 1024 + col]);
        sb1[idx] = tf32_of(nn_w[(k + 4) * 1024 + col]);
    }
    for (int idx = tid; idx < 512; idx += 128) {
        const float2 v = *(const float2*)(nn_b + 2 * idx);
        sbias[idx] = pack2(v.x, v.y);
    }
    __syncthreads();

    const int lane = tid & 31;
    const int warp = tid >> 5;
    const int g4 = lane >> 2;
    const int t4 = lane & 3;
    const int nGroups = N_EDGES / 16;   // 12500, exact

    for (int g = blockIdx.x * 4 + warp; g < nGroups; g += gridDim.x * 4) {
        const int e0 = g * 16;

        if (lane < 16) {
            ssrc[warp][lane] = edge_index[e0 + lane];
            sdst[warp][lane] = edge_index[N_EDGES + e0 + lane];
        }
        __syncwarp();

        // stage x rows: lane -> edge lane>>1, half lane&1 (16 feats)
        {
            const int e = lane >> 1, hf = lane & 1;
            const float4* xr = (const float4*)(x + (size_t)ssrc[warp][e] * IN_C + hf * 16);
            float* dx = &xs[warp][e][hf * 16];
            #pragma unroll
            for (int q = 0; q < 4; ++q) {
                const float4 v = xr[q];
                dx[q * 4 + 0] = v.x; dx[q * 4 + 1] = v.y;
                dx[q * 4 + 2] = v.z; dx[q * 4 + 3] = v.w;
            }
        }

        // A fragments from gmem (small, L1-hot)
        const float* eaP = edge_attr + (size_t)e0 * EDGE_DIM;
        const unsigned a0 = tf32_of(eaP[g4 * 8 + t4]);
        const unsigned a1 = tf32_of(eaP[(g4 + 8) * 8 + t4]);
        const unsigned a2 = tf32_of(eaP[g4 * 8 + t4 + 4]);
        const unsigned a3 = tf32_of(eaP[(g4 + 8) * 8 + t4 + 4]);
        __syncwarp();

        const int dstA = sdst[warp][g4] * HID;
        const int dstB = sdst[warp][g4 + 8] * HID;

        float msgA[8], msgB[8];
        #pragma unroll
        for (int m = 0; m < 8; ++m) { msgA[m] = 0.f; msgB[m] = 0.f; }

        #pragma unroll 4
        for (int i = 0; i < IN_C; ++i) {
            const float xv0 = xs[warp][g4][i];
            const float xv1 = xs[warp][g4 + 8][i];
            #pragma unroll
            for (int c = 0; c < 4; ++c) {
                const int t = i * 4 + c;
                const int colb = (8 * t + g4) * 4 + t4;
                const unsigned b0 = sb0[colb];
                const unsigned b1 = sb1[colb];
                const u64 cb = sbias[4 * t + t4];
                float d0 = lo2(cb), d1 = hi2(cb), d2 = d0, d3 = d1;
                asm("mma.sync.aligned.m16n8k8.row.col.f32.tf32.tf32.f32 "
                    "{%0,%1,%2,%3}, {%4,%5,%6,%7}, {%8,%9}, {%0,%1,%2,%3};"
                    : "+f"(d0), "+f"(d1), "+f"(d2), "+f"(d3)
                    : "r"(a0), "r"(a1), "r"(a2), "r"(a3), "r"(b0), "r"(b1));
                d0 = fmaxf(d0, 0.f); d1 = fmaxf(d1, 0.f);
                d2 = fmaxf(d2, 0.f); d3 = fmaxf(d3, 0.f);
                msgA[2 * c + 0] = fmaf(xv0, d0, msgA[2 * c + 0]);
                msgA[2 * c + 1] = fmaf(xv0, d1, msgA[2 * c + 1]);
                msgB[2 * c + 0] = fmaf(xv1, d2, msgB[2 * c + 0]);
                msgB[2 * c + 1] = fmaf(xv1, d3, msgB[2 * c + 1]);
            }
        }

        #pragma unroll
        for (int c = 0; c < 4; ++c) {
            const int o = 8 * c + 2 * t4;
            red2(&g_agg[dstA + o], msgA[2 * c + 0], msgA[2 * c + 1]);
            red2(&g_agg[dstB + o], msgB[2 * c + 0], msgB[2 * c + 1]);
        }
        __syncwarp();   // protect ssrc/xs before next iteration's overwrite
    }
}

// ---------------------------------------------------------------------------
// Node kernel, 2 lanes per node. Lane sub = t & 1 owns features
// [16*sub, 16*sub+16) as 8 packed pairs. Pair shfl.xor(1) reductions (18
// SHFLs total). x consumed in two 16-feature chunks to bound live registers.
// Resets g_agg after consuming (replaces zero kernel).
// ---------------------------------------------------------------------------
__global__ __launch_bounds__(256) void node_kernel(
    const float* __restrict__ x,
    const float* __restrict__ root,
    const float* __restrict__ bias,
    const float* __restrict__ norm_w,
    const float* __restrict__ norm_b,
    const float* __restrict__ lin_w,
    const float* __restrict__ lin_b,
    float* __restrict__ out)
{
    __shared__ u64 root2[IN_C * 16];   // root packed: [i][pair]
    __shared__ u64 lw2[HID * 8];       // lin_w packed: [k][opair]
    __shared__ u64 bias2[16], nw2[16], nb2[16];
    __shared__ float lb_s[OUT_C];

    const int tid = threadIdx.x;
    for (int idx = tid; idx < IN_C * 16; idx += 256) {
        const int i = idx >> 4, pr = idx & 15;
        const float2 v = *(const float2*)(root + i * HID + 2 * pr);
        root2[idx] = pack2(v.x, v.y);
    }
    for (int idx = tid; idx < HID * 8; idx += 256) {
        const int k = idx >> 3, op = idx & 7;
        const float2 v = *(const float2*)(lin_w + k * OUT_C + 2 * op);
        lw2[idx] = pack2(v.x, v.y);
    }
    if (tid < 16) {
        const float2 b = *(const float2*)(bias + 2 * tid);
        const float2 w = *(const float2*)(norm_w + 2 * tid);
        const float2 nb = *(const float2*)(norm_b + 2 * tid);
        bias2[tid] = pack2(b.x, b.y);
        nw2[tid]   = pack2(w.x, w.y);
        nb2[tid]   = pack2(nb.x, nb.y);
    }
    if (tid < OUT_C) lb_s[tid] = lin_b[tid];
    __syncthreads();

    const int t = blockIdx.x * 256 + tid;
    const int rawNode = t >> 1;
    const bool valid = rawNode < N_NODES;
    const int node = valid ? rawNode : (N_NODES - 1);
    const int sub  = t & 1;
    const int fb   = sub * 16;           // feature base
    const int pb   = sub * 8;            // pair base

    const float4* aggp = (const float4*)(g_agg + (size_t)node * HID + fb);
    u64 h2[8];
    #pragma unroll
    for (int q = 0; q < 4; ++q) {
        const float4 a = aggp[q];
        h2[2 * q + 0] = add2(pack2(a.x, a.y), bias2[pb + 2 * q + 0]);
        h2[2 * q + 1] = add2(pack2(a.z, a.w), bias2[pb + 2 * q + 1]);
    }

    // h += x @ root, x consumed in two 16-feature chunks
    const float4* xp = (const float4*)(x + (size_t)node * IN_C);
    const ulonglong2* r2 = (const ulonglong2*)root2;
    #pragma unroll
    for (int half = 0; half < 2; ++half) {
        float xf[16];
        #pragma unroll
        for (int q = 0; q < 4; ++q) {
            const float4 v = xp[half * 4 + q];
            xf[q * 4 + 0] = v.x; xf[q * 4 + 1] = v.y;
            xf[q * 4 + 2] = v.z; xf[q * 4 + 3] = v.w;
        }
        #pragma unroll
        for (int ii = 0; ii < 16; ++ii) {
            const int i = half * 16 + ii;
            const u64 xi2 = dup2(xf[ii]);
            #pragma unroll
            for (int q = 0; q < 4; ++q) {
                const ulonglong2 rr = r2[i * 8 + 4 * sub + q];
                h2[2 * q + 0] = ffma2(xi2, rr.x, h2[2 * q + 0]);
                h2[2 * q + 1] = ffma2(xi2, rr.y, h2[2 * q + 1]);
            }
        }
    }

    // LayerNorm across the pair
    float s = 0.f;
    #pragma unroll
    for (int j = 0; j < 8; ++j) s += lo2(h2[j]) + hi2(h2[j]);
    s += __shfl_xor_sync(0xffffffffu, s, 1);
    const float mu = s * (1.0f / HID);
    const u64 negmu2 = dup2(-mu);

    u64 vacc = 0ull;
    #pragma unroll
    for (int j = 0; j < 8; ++j) {
        h2[j] = add2(h2[j], negmu2);          // h2 now holds d = h - mu
        vacc = ffma2(h2[j], h2[j], vacc);
    }
    float v = lo2(vacc) + hi2(vacc);
    v += __shfl_xor_sync(0xffffffffu, v, 1);
    const float inv = rsqrtf(v * (1.0f / HID) + LN_EPS);
    const u64 inv2 = dup2(inv);

    float h[16];
    #pragma unroll
    for (int j = 0; j < 8; ++j) {
        u64 t2 = ffma2(h2[j], inv2, 0ull);    // d * inv
        t2 = ffma2(t2, nw2[pb + j], nb2[pb + j]);
        h[2 * j + 0] = fmaxf(lo2(t2), 0.f);
        h[2 * j + 1] = fmaxf(hi2(t2), 0.f);
    }

    // partial final linear over this lane's 16 h-features (all 16 outputs)
    u64 res2[8];
    #pragma unroll
    for (int op = 0; op < 8; ++op) res2[op] = 0ull;
    const ulonglong2* l2 = (const ulonglong2*)lw2;
    #pragma unroll
    for (int k = 0; k < 16; ++k) {
        const u64 hv2 = dup2(h[k]);
        #pragma unroll
        for (int q = 0; q < 4; ++q) {
            const ulonglong2 w = l2[(fb + k) * 4 + q];
            res2[2 * q + 0] = ffma2(hv2, w.x, res2[2 * q + 0]);
            res2[2 * q + 1] = ffma2(hv2, w.y, res2[2 * q + 1]);
        }
    }
    // reduce across the pair
    float res[OUT_C];
    #pragma unroll
    for (int op = 0; op < 8; ++op) {
        float rl = lo2(res2[op]), rh = hi2(res2[op]);
        rl += __shfl_xor_sync(0xffffffffu, rl, 1);
        rh += __shfl_xor_sync(0xffffffffu, rh, 1);
        res[2 * op + 0] = rl;
        res[2 * op + 1] = rh;
    }

    // reset accumulator + write outputs
    if (valid) {
        float4* ragg = (float4*)(g_agg + (size_t)node * HID + fb);
        const float4 z4 = make_float4(0.f, 0.f, 0.f, 0.f);
        ragg[0] = z4; ragg[1] = z4; ragg[2] = z4; ragg[3] = z4;
        // lane sub writes outputs [8*sub, 8*sub+8)
        float* op = out + (size_t)node * OUT_C;
        #pragma unroll
        for (int oo = 0; oo < OUT_C; ++oo)
            if ((oo >> 3) == sub) op[oo] = res[oo] + lb_s[oo];
    }
}

extern "C" void kernel_launch(void* const* d_in, const int* in_sizes, int n_in,
                              void* d_out, int out_size) {
    const float* x          = (const float*)d_in[0];
    const int*   edge_index = (const int*)  d_in[1];
    const float* edge_attr  = (const float*)d_in[2];
    const float* nn_w       = (const float*)d_in[3];
    const float* nn_b       = (const float*)d_in[4];
    const float* root       = (const float*)d_in[5];
    const float* bias       = (const float*)d_in[6];
    const float* norm_w     = (const float*)d_in[7];
    const float* norm_b     = (const float*)d_in[8];
    const float* lin_w      = (const float*)d_in[9];
    const float* lin_b      = (const float*)d_in[10];
    float* out = (float*)d_out;

    edge_kernel<<<592, 128>>>(x, edge_index, edge_attr, nn_w, nn_b);
    node_kernel<<<(N_NODES * 2 + 255) / 256, 256>>>(x, root, bias, norm_w, norm_b,
                                                    lin_w, lin_b, out);
}

// round 14
// speedup vs baseline: 1.8467x; 1.0203x over previous
#include <cuda_runtime.h>

#define N_NODES 50000
#define N_EDGES 200000
#define IN_C    32
#define HID     32
#define OUT_C   16
#define EDGE_DIM 8
#define LN_EPS  1e-5f

typedef unsigned long long u64;

// scatter accumulator; zero-initialized at module load; node_kernel re-zeroes
// it after consuming, so the invariant holds across graph replays.
__device__ float g_agg[N_NODES * HID];

__device__ __forceinline__ u64 ffma2(u64 a, u64 b, u64 c) {
    u64 d;
    asm("fma.rn.f32x2 %0, %1, %2, %3;" : "=l"(d) : "l"(a), "l"(b), "l"(c));
    return d;
}
__device__ __forceinline__ u64 add2(u64 a, u64 b) {
    u64 d;
    asm("add.rn.f32x2 %0, %1, %2;" : "=l"(d) : "l"(a), "l"(b));
    return d;
}
__device__ __forceinline__ u64 dup2(float s) {
    unsigned u = __float_as_uint(s);
    return ((u64)u << 32) | (u64)u;
}
__device__ __forceinline__ u64 pack2(float lo, float hi) {
    return ((u64)__float_as_uint(hi) << 32) | (u64)__float_as_uint(lo);
}
__device__ __forceinline__ float lo2(u64 v) { return __uint_as_float((unsigned)v); }
__device__ __forceinline__ float hi2(u64 v) { return __uint_as_float((unsigned)(v >> 32)); }

__device__ __forceinline__ unsigned tf32_of(float f) {
    unsigned r;
    asm("cvt.rna.tf32.f32 %0, %1;" : "=r"(r) : "f"(f));
    return r;
}
// paired no-return reduction (8B-aligned)
__device__ __forceinline__ void red2(float* p, float a, float b) {
    asm volatile("red.global.add.v2.f32 [%0], {%1, %2};"
        :: "l"(p), "f"(a), "f"(b) : "memory");
}

// ---------------------------------------------------------------------------
// Edge kernel: tf32 mma.sync MLP + scalar contraction + v2 reduction scatter.
// MIO-diet vs R12: B fragments (b0,b1) packed in one u64 -> single LDS.64;
// bias re-laid out so each i's 4 c-pairs come from 2 LDS.128 broadcasts.
// ---------------------------------------------------------------------------
__global__ __launch_bounds__(128) void edge_kernel(
    const float* __restrict__ x,
    const int*   __restrict__ edge_index,
    const float* __restrict__ edge_attr,
    const float* __restrict__ nn_w,
    const float* __restrict__ nn_b)
{
    __shared__ u64      sbp[1024 * 4];       // (b1|b0): idx = col*4 + k     32 KB
    __shared__ u64      sbias[512];          // [i*16 + t4*4 + c] bias pair   4 KB
    __shared__ float    xs[4][16][33];       // [warp][edge][feat], padded
    __shared__ int      ssrc[4][16], sdst[4][16];

    const int tid = threadIdx.x;

    for (int idx = tid; idx < 4096; idx += 128) {
        const int col = idx >> 2, k = idx & 3;
        const unsigned b0 = tf32_of(nn_w[k * 1024 + col]);
        const unsigned b1 = tf32_of(nn_w[(k + 4) * 1024 + col]);
        sbp[idx] = ((u64)b1 << 32) | (u64)b0;
    }
    for (int idx = tid; idx < 512; idx += 128) {
        const int i = idx >> 4, r = idx & 15;
        const int tt4 = r >> 2, c = r & 3;
        const int t = i * 4 + c;
        const int col0 = 8 * t + 2 * tt4;
        sbias[idx] = pack2(nn_b[col0], nn_b[col0 + 1]);
    }
    __syncthreads();

    const int lane = tid & 31;
    const int warp = tid >> 5;
    const int g4 = lane >> 2;
    const int t4 = lane & 3;
    const int nGroups = N_EDGES / 16;   // 12500, exact

    for (int g = blockIdx.x * 4 + warp; g < nGroups; g += gridDim.x * 4) {
        const int e0 = g * 16;

        if (lane < 16) {
            ssrc[warp][lane] = edge_index[e0 + lane];
            sdst[warp][lane] = edge_index[N_EDGES + e0 + lane];
        }
        __syncwarp();

        // stage x rows: lane -> edge lane>>1, half lane&1 (16 feats)
        {
            const int e = lane >> 1, hf = lane & 1;
            const float4* xr = (const float4*)(x + (size_t)ssrc[warp][e] * IN_C + hf * 16);
            float* dx = &xs[warp][e][hf * 16];
            #pragma unroll
            for (int q = 0; q < 4; ++q) {
                const float4 v = xr[q];
                dx[q * 4 + 0] = v.x; dx[q * 4 + 1] = v.y;
                dx[q * 4 + 2] = v.z; dx[q * 4 + 3] = v.w;
            }
        }

        // A fragments from gmem (small, L1-hot)
        const float* eaP = edge_attr + (size_t)e0 * EDGE_DIM;
        const unsigned a0 = tf32_of(eaP[g4 * 8 + t4]);
        const unsigned a1 = tf32_of(eaP[(g4 + 8) * 8 + t4]);
        const unsigned a2 = tf32_of(eaP[g4 * 8 + t4 + 4]);
        const unsigned a3 = tf32_of(eaP[(g4 + 8) * 8 + t4 + 4]);
        __syncwarp();

        const int dstA = sdst[warp][g4] * HID;
        const int dstB = sdst[warp][g4 + 8] * HID;

        float msgA[8], msgB[8];
        #pragma unroll
        for (int m = 0; m < 8; ++m) { msgA[m] = 0.f; msgB[m] = 0.f; }

        #pragma unroll 4
        for (int i = 0; i < IN_C; ++i) {
            const float xv0 = xs[warp][g4][i];
            const float xv1 = xs[warp][g4 + 8][i];
            // this i's 4 bias pairs for my t4: two LDS.128 broadcasts
            const ulonglong2* bp = (const ulonglong2*)&sbias[i * 16 + t4 * 4];
            const ulonglong2 cb01 = bp[0];
            const ulonglong2 cb23 = bp[1];
            const u64 cbs[4] = {cb01.x, cb01.y, cb23.x, cb23.y};
            #pragma unroll
            for (int c = 0; c < 4; ++c) {
                const int t = i * 4 + c;
                const u64 bb = sbp[(8 * t + g4) * 4 + t4];   // LDS.64
                const unsigned b0 = (unsigned)bb;
                const unsigned b1 = (unsigned)(bb >> 32);
                float d0 = lo2(cbs[c]), d1 = hi2(cbs[c]), d2 = d0, d3 = d1;
                asm("mma.sync.aligned.m16n8k8.row.col.f32.tf32.tf32.f32 "
                    "{%0,%1,%2,%3}, {%4,%5,%6,%7}, {%8,%9}, {%0,%1,%2,%3};"
                    : "+f"(d0), "+f"(d1), "+f"(d2), "+f"(d3)
                    : "r"(a0), "r"(a1), "r"(a2), "r"(a3), "r"(b0), "r"(b1));
                d0 = fmaxf(d0, 0.f); d1 = fmaxf(d1, 0.f);
                d2 = fmaxf(d2, 0.f); d3 = fmaxf(d3, 0.f);
                msgA[2 * c + 0] = fmaf(xv0, d0, msgA[2 * c + 0]);
                msgA[2 * c + 1] = fmaf(xv0, d1, msgA[2 * c + 1]);
                msgB[2 * c + 0] = fmaf(xv1, d2, msgB[2 * c + 0]);
                msgB[2 * c + 1] = fmaf(xv1, d3, msgB[2 * c + 1]);
            }
        }

        #pragma unroll
        for (int c = 0; c < 4; ++c) {
            const int o = 8 * c + 2 * t4;
            red2(&g_agg[dstA + o], msgA[2 * c + 0], msgA[2 * c + 1]);
            red2(&g_agg[dstB + o], msgB[2 * c + 0], msgB[2 * c + 1]);
        }
        __syncwarp();   // protect ssrc/xs before next iteration's overwrite
    }
}

// ---------------------------------------------------------------------------
// Node kernel (unchanged from R12 measured config).
// ---------------------------------------------------------------------------
__global__ __launch_bounds__(256) void node_kernel(
    const float* __restrict__ x,
    const float* __restrict__ root,
    const float* __restrict__ bias,
    const float* __restrict__ norm_w,
    const float* __restrict__ norm_b,
    const float* __restrict__ lin_w,
    const float* __restrict__ lin_b,
    float* __restrict__ out)
{
    __shared__ u64 root2[IN_C * 16];
    __shared__ u64 lw2[HID * 8];
    __shared__ u64 bias2[16], nw2[16], nb2[16];
    __shared__ float lb_s[OUT_C];

    const int tid = threadIdx.x;
    for (int idx = tid; idx < IN_C * 16; idx += 256) {
        const int i = idx >> 4, pr = idx & 15;
        const float2 v = *(const float2*)(root + i * HID + 2 * pr);
        root2[idx] = pack2(v.x, v.y);
    }
    for (int idx = tid; idx < HID * 8; idx += 256) {
        const int k = idx >> 3, op = idx & 7;
        const float2 v = *(const float2*)(lin_w + k * OUT_C + 2 * op);
        lw2[idx] = pack2(v.x, v.y);
    }
    if (tid < 16) {
        const float2 b = *(const float2*)(bias + 2 * tid);
        const float2 w = *(const float2*)(norm_w + 2 * tid);
        const float2 nb = *(const float2*)(norm_b + 2 * tid);
        bias2[tid] = pack2(b.x, b.y);
        nw2[tid]   = pack2(w.x, w.y);
        nb2[tid]   = pack2(nb.x, nb.y);
    }
    if (tid < OUT_C) lb_s[tid] = lin_b[tid];
    __syncthreads();

    const int t = blockIdx.x * 256 + tid;
    const int rawNode = t >> 1;
    const bool valid = rawNode < N_NODES;
    const int node = valid ? rawNode : (N_NODES - 1);
    const int sub  = t & 1;
    const int fb   = sub * 16;
    const int pb   = sub * 8;

    const float4* aggp = (const float4*)(g_agg + (size_t)node * HID + fb);
    u64 h2[8];
    #pragma unroll
    for (int q = 0; q < 4; ++q) {
        const float4 a = aggp[q];
        h2[2 * q + 0] = add2(pack2(a.x, a.y), bias2[pb + 2 * q + 0]);
        h2[2 * q + 1] = add2(pack2(a.z, a.w), bias2[pb + 2 * q + 1]);
    }

    const float4* xp = (const float4*)(x + (size_t)node * IN_C);
    const ulonglong2* r2 = (const ulonglong2*)root2;
    #pragma unroll
    for (int half = 0; half < 2; ++half) {
        float xf[16];
        #pragma unroll
        for (int q = 0; q < 4; ++q) {
            const float4 v = xp[half * 4 + q];
            xf[q * 4 + 0] = v.x; xf[q * 4 + 1] = v.y;
            xf[q * 4 + 2] = v.z; xf[q * 4 + 3] = v.w;
        }
        #pragma unroll
        for (int ii = 0; ii < 16; ++ii) {
            const int i = half * 16 + ii;
            const u64 xi2 = dup2(xf[ii]);
            #pragma unroll
            for (int q = 0; q < 4; ++q) {
                const ulonglong2 rr = r2[i * 8 + 4 * sub + q];
                h2[2 * q + 0] = ffma2(xi2, rr.x, h2[2 * q + 0]);
                h2[2 * q + 1] = ffma2(xi2, rr.y, h2[2 * q + 1]);
            }
        }
    }

    float s = 0.f;
    #pragma unroll
    for (int j = 0; j < 8; ++j) s += lo2(h2[j]) + hi2(h2[j]);
    s += __shfl_xor_sync(0xffffffffu, s, 1);
    const float mu = s * (1.0f / HID);
    const u64 negmu2 = dup2(-mu);

    u64 vacc = 0ull;
    #pragma unroll
    for (int j = 0; j < 8; ++j) {
        h2[j] = add2(h2[j], negmu2);
        vacc = ffma2(h2[j], h2[j], vacc);
    }
    float v = lo2(vacc) + hi2(vacc);
    v += __shfl_xor_sync(0xffffffffu, v, 1);
    const float inv = rsqrtf(v * (1.0f / HID) + LN_EPS);
    const u64 inv2 = dup2(inv);

    float h[16];
    #pragma unroll
    for (int j = 0; j < 8; ++j) {
        u64 t2 = ffma2(h2[j], inv2, 0ull);
        t2 = ffma2(t2, nw2[pb + j], nb2[pb + j]);
        h[2 * j + 0] = fmaxf(lo2(t2), 0.f);
        h[2 * j + 1] = fmaxf(hi2(t2), 0.f);
    }

    u64 res2[8];
    #pragma unroll
    for (int op = 0; op < 8; ++op) res2[op] = 0ull;
    const ulonglong2* l2 = (const ulonglong2*)lw2;
    #pragma unroll
    for (int k = 0; k < 16; ++k) {
        const u64 hv2 = dup2(h[k]);
        #pragma unroll
        for (int q = 0; q < 4; ++q) {
            const ulonglong2 w = l2[(fb + k) * 4 + q];
            res2[2 * q + 0] = ffma2(hv2, w.x, res2[2 * q + 0]);
            res2[2 * q + 1] = ffma2(hv2, w.y, res2[2 * q + 1]);
        }
    }
    float res[OUT_C];
    #pragma unroll
    for (int op = 0; op < 8; ++op) {
        float rl = lo2(res2[op]), rh = hi2(res2[op]);
        rl += __shfl_xor_sync(0xffffffffu, rl, 1);
        rh += __shfl_xor_sync(0xffffffffu, rh, 1);
        res[2 * op + 0] = rl;
        res[2 * op + 1] = rh;
    }

    if (valid) {
        float4* ragg = (float4*)(g_agg + (size_t)node * HID + fb);
        const float4 z4 = make_float4(0.f, 0.f, 0.f, 0.f);
        ragg[0] = z4; ragg[1] = z4; ragg[2] = z4; ragg[3] = z4;
        float* op = out + (size_t)node * OUT_C;
        #pragma unroll
        for (int oo = 0; oo < OUT_C; ++oo)
            if ((oo >> 3) == sub) op[oo] = res[oo] + lb_s[oo];
    }
}

extern "C" void kernel_launch(void* const* d_in, const int* in_sizes, int n_in,
                              void* d_out, int out_size) {
    const float* x          = (const float*)d_in[0];
    const int*   edge_index = (const int*)  d_in[1];
    const float* edge_attr  = (const float*)d_in[2];
    const float* nn_w       = (const float*)d_in[3];
    const float* nn_b       = (const float*)d_in[4];
    const float* root       = (const float*)d_in[5];
    const float* bias       = (const float*)d_in[6];
    const float* norm_w     = (const float*)d_in[7];
    const float* norm_b     = (const float*)d_in[8];
    const float* lin_w      = (const float*)d_in[9];
    const float* lin_b      = (const float*)d_in[10];
    float* out = (float*)d_out;

    edge_kernel<<<592, 128>>>(x, edge_index, edge_attr, nn_w, nn_b);
    node_kernel<<<(N_NODES * 2 + 255) / 256, 256>>>(x, root, bias, norm_w, norm_b,
                                                    lin_w, lin_b, out);
}